// round 14
// baseline (speedup 1.0000x reference)
#include <cuda_runtime.h>
#include <cstdint>

#define N_PAT   32
#define L_SEQ   2048
#define C_TAB   256
#define DEM_IN  8
#define DEM_H   40
#define DEM_OUT 20
#define OUT_C   788     // 256*3 + 20
#define M_TOT   (N_PAT * L_SEQ)          // 65536
#define SZ_X    ((size_t)M_TOT * C_TAB)  // 16,777,216

// ---- scratch (device globals; no runtime allocation) ----
__device__ float g_x[SZ_X];
__device__ float g_pmax[SZ_X];
__device__ float g_pavg[SZ_X];
__device__ float g_psum[SZ_X];
__device__ float g_nb[N_PAT * C_TAB];    // b_lin + dem contribution, per (n,c)
__device__ float g_d[N_PAT * DEM_OUT];   // dem MLP output

// ---- packed fp32x2 FMA (FFMA2; ptxas won't emit this from C++) ----
__device__ __forceinline__ unsigned long long ffma2(unsigned long long a,
                                                    unsigned long long b,
                                                    unsigned long long c) {
    unsigned long long d;
    asm("fma.rn.f32x2 %0, %1, %2, %3;" : "=l"(d) : "l"(a), "l"(b), "l"(c));
    return d;
}
__device__ __forceinline__ float2 unpack2(unsigned long long a) {
    float2 r;
    asm("mov.b64 {%0, %1}, %2;" : "=f"(r.x), "=f"(r.y) : "l"(a));
    return r;
}

// ============================================================
// Kernel 1: dem MLP (8->40->20, ReLU) + effective bias
//   g_nb[n][c] = b_lin[c] + sum_j d[n][j] * W_lin[1024+j][c]
// ============================================================
__global__ void k_dem(const float* __restrict__ dem,
                      const float* __restrict__ W1, const float* __restrict__ b1,
                      const float* __restrict__ W2, const float* __restrict__ b2,
                      const float* __restrict__ Wl, const float* __restrict__ bl) {
    __shared__ float s_d[N_PAT][DEM_OUT];
    int tid = threadIdx.x;
    if (tid < N_PAT) {
        float h[DEM_H];
#pragma unroll
        for (int j = 0; j < DEM_H; j++) {
            float acc = b1[j];
#pragma unroll
            for (int i = 0; i < DEM_IN; i++)
                acc += dem[tid * DEM_IN + i] * W1[i * DEM_H + j];
            h[j] = fmaxf(acc, 0.0f);
        }
#pragma unroll
        for (int j = 0; j < DEM_OUT; j++) {
            float acc = b2[j];
#pragma unroll
            for (int i = 0; i < DEM_H; i++)
                acc += h[i] * W2[i * DEM_OUT + j];
            float dv = fmaxf(acc, 0.0f);
            s_d[tid][j] = dv;
            g_d[tid * DEM_OUT + j] = dv;
        }
    }
    __syncthreads();
    // tid = channel c (0..255)
    for (int n = 0; n < N_PAT; n++) {
        float acc = bl[tid];
#pragma unroll
        for (int j = 0; j < DEM_OUT; j++)
            acc += s_d[n][j] * Wl[(1024 + j) * C_TAB + tid];
        g_nb[n * C_TAB + tid] = acc;
    }
}

// ============================================================
// Kernel 2: SGEMM  x[m][c] = sum_k ts[m][k] * W[k][c] + nb[n][c]
//   M=65536, K=1024 (4 tables x 256), N=256, fp32, FFMA2-packed.
//   128x128x8 tiles, 8x8 microtile; A duplicated in SMEM so both
//   FFMA2 operands come directly from LDS (no per-k MOV dup).
// ============================================================
__global__ __launch_bounds__(256, 2) void k_gemm(
        const float* __restrict__ t0, const float* __restrict__ t1,
        const float* __restrict__ t2, const float* __restrict__ t3,
        const float* __restrict__ W) {
    __shared__ float As2[8][256];   // [k][2*m_local] duplicated pairs
    __shared__ float Bs[8][128];

    const int tid  = threadIdx.x;
    const int m0   = blockIdx.y * 128;
    const int c0   = blockIdx.x * 128;
    const int arow = tid >> 1;           // 0..127
    const int acol = (tid & 1) * 4;      // 0 or 4
    const int brow = tid >> 5;           // 0..7
    const int bcol = (tid & 31) * 4;     // 0..124
    const int tx   = tid & 15;
    const int ty   = tid >> 4;

    unsigned long long acc[8][4];
#pragma unroll
    for (int i = 0; i < 8; i++)
#pragma unroll
        for (int j = 0; j < 4; j++) acc[i][j] = 0ull;

    auto ldA = [&](int kt) -> float4 {
        int kk = kt * 8;
        const float* A = (kk < 256) ? t0 : (kk < 512) ? t1 : (kk < 768) ? t2 : t3;
        int ko = kk & 255;
        return *(const float4*)(A + (size_t)(m0 + arow) * C_TAB + ko + acol);
    };
    auto ldB = [&](int kt) -> float4 {
        int kk = kt * 8;
        return *(const float4*)(W + (size_t)(kk + brow) * C_TAB + c0 + bcol);
    };

    float4 a4 = ldA(0), b4 = ldB(0);
    for (int kt = 0; kt < 128; ++kt) {
        As2[acol + 0][2 * arow] = a4.x;  As2[acol + 0][2 * arow + 1] = a4.x;
        As2[acol + 1][2 * arow] = a4.y;  As2[acol + 1][2 * arow + 1] = a4.y;
        As2[acol + 2][2 * arow] = a4.z;  As2[acol + 2][2 * arow + 1] = a4.z;
        As2[acol + 3][2 * arow] = a4.w;  As2[acol + 3][2 * arow + 1] = a4.w;
        *(float4*)&Bs[brow][bcol] = b4;
        __syncthreads();
        if (kt < 127) { a4 = ldA(kt + 1); b4 = ldB(kt + 1); }
#pragma unroll
        for (int k = 0; k < 8; k++) {
            unsigned long long ap[8], bp[4];
            const unsigned long long* Ap =
                (const unsigned long long*)&As2[k][ty * 16];
            const unsigned long long* Bp =
                (const unsigned long long*)&Bs[k][tx * 8];
#pragma unroll
            for (int i = 0; i < 8; i++) ap[i] = Ap[i];
#pragma unroll
            for (int j = 0; j < 4; j++) bp[j] = Bp[j];
#pragma unroll
            for (int i = 0; i < 8; i++)
#pragma unroll
                for (int j = 0; j < 4; j++)
                    acc[i][j] = ffma2(ap[i], bp[j], acc[i][j]);
        }
        __syncthreads();
    }

    // epilogue: add per-(n,c) effective bias, store x
    const int n = m0 >> 11;   // 128 | 2048 -> constant n per block
    float nb[8];
#pragma unroll
    for (int j = 0; j < 8; j++) nb[j] = g_nb[n * C_TAB + c0 + tx * 8 + j];
#pragma unroll
    for (int i = 0; i < 8; i++) {
        size_t row = (size_t)(m0 + ty * 8 + i) * C_TAB + c0 + tx * 8;
        float v[8];
#pragma unroll
        for (int j = 0; j < 4; j++) {
            float2 p = unpack2(acc[i][j]);
            v[2 * j]     = p.x + nb[2 * j];
            v[2 * j + 1] = p.y + nb[2 * j + 1];
        }
        *(float4*)&g_x[row]     = make_float4(v[0], v[1], v[2], v[3]);
        *(float4*)&g_x[row + 4] = make_float4(v[4], v[5], v[6], v[7]);
    }
}

// ============================================================
// Kernel 3: causal pools. One block per n, 256 threads = channels.
// Sequential over l; writes p_max/p_avg/p_sum [n][l][c] coalesced,
// activations + time_inds [n][c][l] via SMEM transpose tiles.
// ============================================================
__global__ __launch_bounds__(256) void k_scan(float* __restrict__ tind_out,
                                              float* __restrict__ act_out) {
    const int n = blockIdx.x;
    const int c = threadIdx.x;
    __shared__ float s_act[256][17];
    __shared__ int   s_idx[256][17];

    float cmax = __int_as_float(0xff800000);  // -inf
    int   carg = 0;
    float csum = 0.0f;

    const float* xp  = g_x    + (size_t)n * L_SEQ * C_TAB + c;
    float* pm_p      = g_pmax + (size_t)n * L_SEQ * C_TAB + c;
    float* pa_p      = g_pavg + (size_t)n * L_SEQ * C_TAB + c;
    float* ps_p      = g_psum + (size_t)n * L_SEQ * C_TAB + c;
    const size_t obase = (size_t)n * C_TAB * L_SEQ;

    for (int l0 = 0; l0 < L_SEQ; l0 += 16) {
#pragma unroll
        for (int j = 0; j < 16; j++) {
            int l = l0 + j;
            float v = xp[(size_t)l * C_TAB];
            if (v > cmax) { cmax = v; carg = l; }   // first-occurrence ties
            csum += v;
            bool pad = (l < L_SEQ - 1);
            float pm = pad ? fmaxf(cmax, 0.0f) : cmax;
            int   ti = (pad && (cmax <= 0.0f)) ? (l - (L_SEQ - 1)) : carg;
            pm_p[(size_t)l * C_TAB] = pm;
            pa_p[(size_t)l * C_TAB] = csum * (1.0f / (float)L_SEQ);
            ps_p[(size_t)l * C_TAB] = csum * rsqrtf((float)(l + 1));
            s_act[c][j] = pm;
            s_idx[c][j] = ti;
        }
        __syncthreads();
        int jj = c & 15;
        int r0 = c >> 4;
#pragma unroll
        for (int i = 0; i < 16; i++) {
            int c2 = r0 * 16 + i;
            size_t off = obase + (size_t)c2 * L_SEQ + l0 + jj;
            act_out[off]  = s_act[c2][jj];
            tind_out[off] = (float)s_idx[c2][jj];
        }
        __syncthreads();
    }
}

// ============================================================
// Kernel 4: LayerNorm over channels + assemble output rows.
// One block per (n,l) row; fused 6-way reduction.
// ============================================================
__global__ __launch_bounds__(256) void k_ln(float* __restrict__ out) {
    const int m = blockIdx.x;       // 0..65535
    const int c = threadIdx.x;
    const size_t base = (size_t)m * C_TAB + c;
    float vm = g_pmax[base];
    float va = g_pavg[base];
    float vs = g_psum[base];

    float s[6] = { vm, vm * vm, va, va * va, vs, vs * vs };
#pragma unroll
    for (int o = 16; o > 0; o >>= 1)
#pragma unroll
        for (int q = 0; q < 6; q++)
            s[q] += __shfl_xor_sync(0xffffffffu, s[q], o);

    __shared__ float red[8][6];
    int warp = c >> 5, lane = c & 31;
    if (lane == 0) {
#pragma unroll
        for (int q = 0; q < 6; q++) red[warp][q] = s[q];
    }
    __syncthreads();
    float t[6];
#pragma unroll
    for (int q = 0; q < 6; q++) {
        float a = 0.0f;
#pragma unroll
        for (int w = 0; w < 8; w++) a += red[w][q];
        t[q] = a;
    }
    const float inv = 1.0f / (float)C_TAB;
    float mu_m = t[0] * inv, var_m = t[1] * inv - mu_m * mu_m;
    float mu_a = t[2] * inv, var_a = t[3] * inv - mu_a * mu_a;
    float mu_s = t[4] * inv, var_s = t[5] * inv - mu_s * mu_s;
    float rs_m = rsqrtf(var_m + 1e-5f);
    float rs_a = rsqrtf(var_a + 1e-5f);
    float rs_s = rsqrtf(var_s + 1e-5f);

    const size_t ob = (size_t)m * OUT_C;
    out[ob + c]       = (vm - mu_m) * rs_m;
    out[ob + 256 + c] = (va - mu_a) * rs_a;
    out[ob + 512 + c] = (vs - mu_s) * rs_s;
    if (c < DEM_OUT)
        out[ob + 768 + c] = g_d[(m >> 11) * DEM_OUT + c];
}

// ============================================================
extern "C" void kernel_launch(void* const* d_in, const int* in_sizes, int n_in,
                              void* d_out, int out_size) {
    (void)in_sizes; (void)n_in; (void)out_size;
    const float* dem = (const float*)d_in[0];
    const float* t0  = (const float*)d_in[1];
    const float* t1  = (const float*)d_in[2];
    const float* t2  = (const float*)d_in[3];
    const float* t3  = (const float*)d_in[4];
    const float* W1  = (const float*)d_in[5];
    const float* b1  = (const float*)d_in[6];
    const float* W2  = (const float*)d_in[7];
    const float* b2  = (const float*)d_in[8];
    const float* Wl  = (const float*)d_in[9];
    const float* bl  = (const float*)d_in[10];

    float* out  = (float*)d_out;                                   // [32,2048,788]
    float* tind = out  + (size_t)N_PAT * L_SEQ * OUT_C;            // [32,256,2048]
    float* act  = tind + (size_t)N_PAT * C_TAB * L_SEQ;            // [32,256,2048]

    k_dem<<<1, 256>>>(dem, W1, b1, W2, b2, Wl, bl);
    k_gemm<<<dim3(2, 512), 256>>>(t0, t1, t2, t3, Wl);
    k_scan<<<N_PAT, 256>>>(tind, act);
    k_ln<<<M_TOT, 256>>>(out);
}

// round 15
// speedup vs baseline: 1.0018x; 1.0018x over previous
#include <cuda_runtime.h>
#include <cstdint>

#define N_PAT   32
#define L_SEQ   2048
#define C_TAB   256
#define DEM_IN  8
#define DEM_H   40
#define DEM_OUT 20
#define OUT_C   788     // 256*3 + 20
#define M_TOT   (N_PAT * L_SEQ)          // 65536
#define SZ_X    ((size_t)M_TOT * C_TAB)  // 16,777,216

// ---- scratch (device globals; no runtime allocation) ----
__device__ float g_x[SZ_X];
__device__ float g_pmax[SZ_X];
__device__ float g_pavg[SZ_X];
__device__ float g_psum[SZ_X];
__device__ float g_nb[N_PAT * C_TAB];    // b_lin + dem contribution, per (n,c)
__device__ float g_d[N_PAT * DEM_OUT];   // dem MLP output

// ---- packed fp32x2 FMA (FFMA2; ptxas won't emit this from C++) ----
__device__ __forceinline__ unsigned long long ffma2(unsigned long long a,
                                                    unsigned long long b,
                                                    unsigned long long c) {
    unsigned long long d;
    asm("fma.rn.f32x2 %0, %1, %2, %3;" : "=l"(d) : "l"(a), "l"(b), "l"(c));
    return d;
}
__device__ __forceinline__ float2 unpack2(unsigned long long a) {
    float2 r;
    asm("mov.b64 {%0, %1}, %2;" : "=f"(r.x), "=f"(r.y) : "l"(a));
    return r;
}

// ============================================================
// Kernel 1: dem MLP (8->40->20, ReLU) + effective bias
//   g_nb[n][c] = b_lin[c] + sum_j d[n][j] * W_lin[1024+j][c]
// ============================================================
__global__ void k_dem(const float* __restrict__ dem,
                      const float* __restrict__ W1, const float* __restrict__ b1,
                      const float* __restrict__ W2, const float* __restrict__ b2,
                      const float* __restrict__ Wl, const float* __restrict__ bl) {
    __shared__ float s_d[N_PAT][DEM_OUT];
    int tid = threadIdx.x;
    if (tid < N_PAT) {
        float h[DEM_H];
#pragma unroll
        for (int j = 0; j < DEM_H; j++) {
            float acc = b1[j];
#pragma unroll
            for (int i = 0; i < DEM_IN; i++)
                acc += dem[tid * DEM_IN + i] * W1[i * DEM_H + j];
            h[j] = fmaxf(acc, 0.0f);
        }
#pragma unroll
        for (int j = 0; j < DEM_OUT; j++) {
            float acc = b2[j];
#pragma unroll
            for (int i = 0; i < DEM_H; i++)
                acc += h[i] * W2[i * DEM_OUT + j];
            float dv = fmaxf(acc, 0.0f);
            s_d[tid][j] = dv;
            g_d[tid * DEM_OUT + j] = dv;
        }
    }
    __syncthreads();
    // tid = channel c (0..255)
    for (int n = 0; n < N_PAT; n++) {
        float acc = bl[tid];
#pragma unroll
        for (int j = 0; j < DEM_OUT; j++)
            acc += s_d[n][j] * Wl[(1024 + j) * C_TAB + tid];
        g_nb[n * C_TAB + tid] = acc;
    }
}

// ============================================================
// Kernel 2: SGEMM  x[m][c] = sum_k ts[m][k] * W[k][c] + nb[n][c]
//   M=65536, K=1024 (4 tables x 256), N=256, fp32, FFMA2-packed.
//   128x128x8 tiles, 8x8 microtile; A duplicated in SMEM so both
//   FFMA2 operands come directly from LDS (no per-k MOV dup).
// ============================================================
__global__ __launch_bounds__(256, 2) void k_gemm(
        const float* __restrict__ t0, const float* __restrict__ t1,
        const float* __restrict__ t2, const float* __restrict__ t3,
        const float* __restrict__ W) {
    __shared__ float As2[8][256];   // [k][2*m_local] duplicated pairs
    __shared__ float Bs[8][128];

    const int tid  = threadIdx.x;
    const int m0   = blockIdx.y * 128;
    const int c0   = blockIdx.x * 128;
    const int arow = tid >> 1;           // 0..127
    const int acol = (tid & 1) * 4;      // 0 or 4
    const int brow = tid >> 5;           // 0..7
    const int bcol = (tid & 31) * 4;     // 0..124
    const int tx   = tid & 15;
    const int ty   = tid >> 4;

    unsigned long long acc[8][4];
#pragma unroll
    for (int i = 0; i < 8; i++)
#pragma unroll
        for (int j = 0; j < 4; j++) acc[i][j] = 0ull;

    auto ldA = [&](int kt) -> float4 {
        int kk = kt * 8;
        const float* A = (kk < 256) ? t0 : (kk < 512) ? t1 : (kk < 768) ? t2 : t3;
        int ko = kk & 255;
        return *(const float4*)(A + (size_t)(m0 + arow) * C_TAB + ko + acol);
    };
    auto ldB = [&](int kt) -> float4 {
        int kk = kt * 8;
        return *(const float4*)(W + (size_t)(kk + brow) * C_TAB + c0 + bcol);
    };

    float4 a4 = ldA(0), b4 = ldB(0);
    for (int kt = 0; kt < 128; ++kt) {
        As2[acol + 0][2 * arow] = a4.x;  As2[acol + 0][2 * arow + 1] = a4.x;
        As2[acol + 1][2 * arow] = a4.y;  As2[acol + 1][2 * arow + 1] = a4.y;
        As2[acol + 2][2 * arow] = a4.z;  As2[acol + 2][2 * arow + 1] = a4.z;
        As2[acol + 3][2 * arow] = a4.w;  As2[acol + 3][2 * arow + 1] = a4.w;
        *(float4*)&Bs[brow][bcol] = b4;
        __syncthreads();
        if (kt < 127) { a4 = ldA(kt + 1); b4 = ldB(kt + 1); }
#pragma unroll
        for (int k = 0; k < 8; k++) {
            unsigned long long ap[8], bp[4];
            const unsigned long long* Ap =
                (const unsigned long long*)&As2[k][ty * 16];
            const unsigned long long* Bp =
                (const unsigned long long*)&Bs[k][tx * 8];
#pragma unroll
            for (int i = 0; i < 8; i++) ap[i] = Ap[i];
#pragma unroll
            for (int j = 0; j < 4; j++) bp[j] = Bp[j];
#pragma unroll
            for (int i = 0; i < 8; i++)
#pragma unroll
                for (int j = 0; j < 4; j++)
                    acc[i][j] = ffma2(ap[i], bp[j], acc[i][j]);
        }
        __syncthreads();
    }

    // epilogue: add per-(n,c) effective bias, store x
    const int n = m0 >> 11;   // 128 | 2048 -> constant n per block
    float nb[8];
#pragma unroll
    for (int j = 0; j < 8; j++) nb[j] = g_nb[n * C_TAB + c0 + tx * 8 + j];
#pragma unroll
    for (int i = 0; i < 8; i++) {
        size_t row = (size_t)(m0 + ty * 8 + i) * C_TAB + c0 + tx * 8;
        float v[8];
#pragma unroll
        for (int j = 0; j < 4; j++) {
            float2 p = unpack2(acc[i][j]);
            v[2 * j]     = p.x + nb[2 * j];
            v[2 * j + 1] = p.y + nb[2 * j + 1];
        }
        *(float4*)&g_x[row]     = make_float4(v[0], v[1], v[2], v[3]);
        *(float4*)&g_x[row + 4] = make_float4(v[4], v[5], v[6], v[7]);
    }
}

// ============================================================
// Kernel 3: causal pools. One block per n, 256 threads = channels.
// Sequential over l; writes p_max/p_avg/p_sum [n][l][c] coalesced,
// activations + time_inds [n][c][l] via SMEM transpose tiles.
// ============================================================
__global__ __launch_bounds__(256) void k_scan(float* __restrict__ tind_out,
                                              float* __restrict__ act_out) {
    const int n = blockIdx.x;
    const int c = threadIdx.x;
    __shared__ float s_act[256][17];
    __shared__ int   s_idx[256][17];

    float cmax = __int_as_float(0xff800000);  // -inf
    int   carg = 0;
    float csum = 0.0f;

    const float* xp  = g_x    + (size_t)n * L_SEQ * C_TAB + c;
    float* pm_p      = g_pmax + (size_t)n * L_SEQ * C_TAB + c;
    float* pa_p      = g_pavg + (size_t)n * L_SEQ * C_TAB + c;
    float* ps_p      = g_psum + (size_t)n * L_SEQ * C_TAB + c;
    const size_t obase = (size_t)n * C_TAB * L_SEQ;

    for (int l0 = 0; l0 < L_SEQ; l0 += 16) {
#pragma unroll
        for (int j = 0; j < 16; j++) {
            int l = l0 + j;
            float v = xp[(size_t)l * C_TAB];
            if (v > cmax) { cmax = v; carg = l; }   // first-occurrence ties
            csum += v;
            bool pad = (l < L_SEQ - 1);
            float pm = pad ? fmaxf(cmax, 0.0f) : cmax;
            int   ti = (pad && (cmax <= 0.0f)) ? (l - (L_SEQ - 1)) : carg;
            pm_p[(size_t)l * C_TAB] = pm;
            pa_p[(size_t)l * C_TAB] = csum * (1.0f / (float)L_SEQ);
            ps_p[(size_t)l * C_TAB] = csum * rsqrtf((float)(l + 1));
            s_act[c][j] = pm;
            s_idx[c][j] = ti;
        }
        __syncthreads();
        int jj = c & 15;
        int r0 = c >> 4;
#pragma unroll
        for (int i = 0; i < 16; i++) {
            int c2 = r0 * 16 + i;
            size_t off = obase + (size_t)c2 * L_SEQ + l0 + jj;
            act_out[off]  = s_act[c2][jj];
            tind_out[off] = (float)s_idx[c2][jj];
        }
        __syncthreads();
    }
}

// ============================================================
// Kernel 4: LayerNorm over channels + assemble output rows.
// One block per (n,l) row; fused 6-way reduction.
// ============================================================
__global__ __launch_bounds__(256) void k_ln(float* __restrict__ out) {
    const int m = blockIdx.x;       // 0..65535
    const int c = threadIdx.x;
    const size_t base = (size_t)m * C_TAB + c;
    float vm = g_pmax[base];
    float va = g_pavg[base];
    float vs = g_psum[base];

    float s[6] = { vm, vm * vm, va, va * va, vs, vs * vs };
#pragma unroll
    for (int o = 16; o > 0; o >>= 1)
#pragma unroll
        for (int q = 0; q < 6; q++)
            s[q] += __shfl_xor_sync(0xffffffffu, s[q], o);

    __shared__ float red[8][6];
    int warp = c >> 5, lane = c & 31;
    if (lane == 0) {
#pragma unroll
        for (int q = 0; q < 6; q++) red[warp][q] = s[q];
    }
    __syncthreads();
    float t[6];
#pragma unroll
    for (int q = 0; q < 6; q++) {
        float a = 0.0f;
#pragma unroll
        for (int w = 0; w < 8; w++) a += red[w][q];
        t[q] = a;
    }
    const float inv = 1.0f / (float)C_TAB;
    float mu_m = t[0] * inv, var_m = t[1] * inv - mu_m * mu_m;
    float mu_a = t[2] * inv, var_a = t[3] * inv - mu_a * mu_a;
    float mu_s = t[4] * inv, var_s = t[5] * inv - mu_s * mu_s;
    float rs_m = rsqrtf(var_m + 1e-5f);
    float rs_a = rsqrtf(var_a + 1e-5f);
    float rs_s = rsqrtf(var_s + 1e-5f);

    const size_t ob = (size_t)m * OUT_C;
    out[ob + c]       = (vm - mu_m) * rs_m;
    out[ob + 256 + c] = (va - mu_a) * rs_a;
    out[ob + 512 + c] = (vs - mu_s) * rs_s;
    if (c < DEM_OUT)
        out[ob + 768 + c] = g_d[(m >> 11) * DEM_OUT + c];
}

// ============================================================
extern "C" void kernel_launch(void* const* d_in, const int* in_sizes, int n_in,
                              void* d_out, int out_size) {
    (void)in_sizes; (void)n_in; (void)out_size;
    const float* dem = (const float*)d_in[0];
    const float* t0  = (const float*)d_in[1];
    const float* t1  = (const float*)d_in[2];
    const float* t2  = (const float*)d_in[3];
    const float* t3  = (const float*)d_in[4];
    const float* W1  = (const float*)d_in[5];
    const float* b1  = (const float*)d_in[6];
    const float* W2  = (const float*)d_in[7];
    const float* b2  = (const float*)d_in[8];
    const float* Wl  = (const float*)d_in[9];
    const float* bl  = (const float*)d_in[10];

    float* out  = (float*)d_out;                                   // [32,2048,788]
    float* tind = out  + (size_t)N_PAT * L_SEQ * OUT_C;            // [32,256,2048]
    float* act  = tind + (size_t)N_PAT * C_TAB * L_SEQ;            // [32,256,2048]

    k_dem<<<1, 256>>>(dem, W1, b1, W2, b2, Wl, bl);
    k_gemm<<<dim3(2, 512), 256>>>(t0, t1, t2, t3, Wl);
    k_scan<<<N_PAT, 256>>>(tind, act);
    k_ln<<<M_TOT, 256>>>(out);
}

// round 16
// speedup vs baseline: 1.0028x; 1.0010x over previous
#include <cuda_runtime.h>
#include <cstdint>

#define N_PAT   32
#define L_SEQ   2048
#define C_TAB   256
#define DEM_IN  8
#define DEM_H   40
#define DEM_OUT 20
#define OUT_C   788     // 256*3 + 20
#define M_TOT   (N_PAT * L_SEQ)          // 65536
#define SZ_X    ((size_t)M_TOT * C_TAB)  // 16,777,216

// ---- scratch (device globals; no runtime allocation) ----
__device__ float g_x[SZ_X];
__device__ float g_pmax[SZ_X];
__device__ float g_pavg[SZ_X];
__device__ float g_psum[SZ_X];
__device__ float g_nb[N_PAT * C_TAB];    // b_lin + dem contribution, per (n,c)
__device__ float g_d[N_PAT * DEM_OUT];   // dem MLP output

// ---- packed fp32x2 FMA (FFMA2; ptxas won't emit this from C++) ----
__device__ __forceinline__ unsigned long long ffma2(unsigned long long a,
                                                    unsigned long long b,
                                                    unsigned long long c) {
    unsigned long long d;
    asm("fma.rn.f32x2 %0, %1, %2, %3;" : "=l"(d) : "l"(a), "l"(b), "l"(c));
    return d;
}
__device__ __forceinline__ float2 unpack2(unsigned long long a) {
    float2 r;
    asm("mov.b64 {%0, %1}, %2;" : "=f"(r.x), "=f"(r.y) : "l"(a));
    return r;
}

// ============================================================
// Kernel 1: dem MLP (8->40->20, ReLU) + effective bias
//   g_nb[n][c] = b_lin[c] + sum_j d[n][j] * W_lin[1024+j][c]
// ============================================================
__global__ void k_dem(const float* __restrict__ dem,
                      const float* __restrict__ W1, const float* __restrict__ b1,
                      const float* __restrict__ W2, const float* __restrict__ b2,
                      const float* __restrict__ Wl, const float* __restrict__ bl) {
    __shared__ float s_d[N_PAT][DEM_OUT];
    int tid = threadIdx.x;
    if (tid < N_PAT) {
        float h[DEM_H];
#pragma unroll
        for (int j = 0; j < DEM_H; j++) {
            float acc = b1[j];
#pragma unroll
            for (int i = 0; i < DEM_IN; i++)
                acc += dem[tid * DEM_IN + i] * W1[i * DEM_H + j];
            h[j] = fmaxf(acc, 0.0f);
        }
#pragma unroll
        for (int j = 0; j < DEM_OUT; j++) {
            float acc = b2[j];
#pragma unroll
            for (int i = 0; i < DEM_H; i++)
                acc += h[i] * W2[i * DEM_OUT + j];
            float dv = fmaxf(acc, 0.0f);
            s_d[tid][j] = dv;
            g_d[tid * DEM_OUT + j] = dv;
        }
    }
    __syncthreads();
    // tid = channel c (0..255)
    for (int n = 0; n < N_PAT; n++) {
        float acc = bl[tid];
#pragma unroll
        for (int j = 0; j < DEM_OUT; j++)
            acc += s_d[n][j] * Wl[(1024 + j) * C_TAB + tid];
        g_nb[n * C_TAB + tid] = acc;
    }
}

// ============================================================
// Kernel 2: SGEMM  x[m][c] = sum_k ts[m][k] * W[k][c] + nb[n][c]
//   M=65536, K=1024 (4 tables x 256), N=256, fp32, FFMA2-packed.
//   128x128x8 tiles, 8x8 microtile; A duplicated in SMEM so both
//   FFMA2 operands come directly from LDS (no per-k MOV dup).
// ============================================================
__global__ __launch_bounds__(256, 2) void k_gemm(
        const float* __restrict__ t0, const float* __restrict__ t1,
        const float* __restrict__ t2, const float* __restrict__ t3,
        const float* __restrict__ W) {
    __shared__ float As2[8][256];   // [k][2*m_local] duplicated pairs
    __shared__ float Bs[8][128];

    const int tid  = threadIdx.x;
    const int m0   = blockIdx.y * 128;
    const int c0   = blockIdx.x * 128;
    const int arow = tid >> 1;           // 0..127
    const int acol = (tid & 1) * 4;      // 0 or 4
    const int brow = tid >> 5;           // 0..7
    const int bcol = (tid & 31) * 4;     // 0..124
    const int tx   = tid & 15;
    const int ty   = tid >> 4;

    unsigned long long acc[8][4];
#pragma unroll
    for (int i = 0; i < 8; i++)
#pragma unroll
        for (int j = 0; j < 4; j++) acc[i][j] = 0ull;

    auto ldA = [&](int kt) -> float4 {
        int kk = kt * 8;
        const float* A = (kk < 256) ? t0 : (kk < 512) ? t1 : (kk < 768) ? t2 : t3;
        int ko = kk & 255;
        return *(const float4*)(A + (size_t)(m0 + arow) * C_TAB + ko + acol);
    };
    auto ldB = [&](int kt) -> float4 {
        int kk = kt * 8;
        return *(const float4*)(W + (size_t)(kk + brow) * C_TAB + c0 + bcol);
    };

    float4 a4 = ldA(0), b4 = ldB(0);
    for (int kt = 0; kt < 128; ++kt) {
        As2[acol + 0][2 * arow] = a4.x;  As2[acol + 0][2 * arow + 1] = a4.x;
        As2[acol + 1][2 * arow] = a4.y;  As2[acol + 1][2 * arow + 1] = a4.y;
        As2[acol + 2][2 * arow] = a4.z;  As2[acol + 2][2 * arow + 1] = a4.z;
        As2[acol + 3][2 * arow] = a4.w;  As2[acol + 3][2 * arow + 1] = a4.w;
        *(float4*)&Bs[brow][bcol] = b4;
        __syncthreads();
        if (kt < 127) { a4 = ldA(kt + 1); b4 = ldB(kt + 1); }
#pragma unroll
        for (int k = 0; k < 8; k++) {
            unsigned long long ap[8], bp[4];
            const unsigned long long* Ap =
                (const unsigned long long*)&As2[k][ty * 16];
            const unsigned long long* Bp =
                (const unsigned long long*)&Bs[k][tx * 8];
#pragma unroll
            for (int i = 0; i < 8; i++) ap[i] = Ap[i];
#pragma unroll
            for (int j = 0; j < 4; j++) bp[j] = Bp[j];
#pragma unroll
            for (int i = 0; i < 8; i++)
#pragma unroll
                for (int j = 0; j < 4; j++)
                    acc[i][j] = ffma2(ap[i], bp[j], acc[i][j]);
        }
        __syncthreads();
    }

    // epilogue: add per-(n,c) effective bias, store x
    const int n = m0 >> 11;   // 128 | 2048 -> constant n per block
    float nb[8];
#pragma unroll
    for (int j = 0; j < 8; j++) nb[j] = g_nb[n * C_TAB + c0 + tx * 8 + j];
#pragma unroll
    for (int i = 0; i < 8; i++) {
        size_t row = (size_t)(m0 + ty * 8 + i) * C_TAB + c0 + tx * 8;
        float v[8];
#pragma unroll
        for (int j = 0; j < 4; j++) {
            float2 p = unpack2(acc[i][j]);
            v[2 * j]     = p.x + nb[2 * j];
            v[2 * j + 1] = p.y + nb[2 * j + 1];
        }
        *(float4*)&g_x[row]     = make_float4(v[0], v[1], v[2], v[3]);
        *(float4*)&g_x[row + 4] = make_float4(v[4], v[5], v[6], v[7]);
    }
}

// ============================================================
// Kernel 3: causal pools. One block per n, 256 threads = channels.
// Sequential over l; writes p_max/p_avg/p_sum [n][l][c] coalesced,
// activations + time_inds [n][c][l] via SMEM transpose tiles.
// ============================================================
__global__ __launch_bounds__(256) void k_scan(float* __restrict__ tind_out,
                                              float* __restrict__ act_out) {
    const int n = blockIdx.x;
    const int c = threadIdx.x;
    __shared__ float s_act[256][17];
    __shared__ int   s_idx[256][17];

    float cmax = __int_as_float(0xff800000);  // -inf
    int   carg = 0;
    float csum = 0.0f;

    const float* xp  = g_x    + (size_t)n * L_SEQ * C_TAB + c;
    float* pm_p      = g_pmax + (size_t)n * L_SEQ * C_TAB + c;
    float* pa_p      = g_pavg + (size_t)n * L_SEQ * C_TAB + c;
    float* ps_p      = g_psum + (size_t)n * L_SEQ * C_TAB + c;
    const size_t obase = (size_t)n * C_TAB * L_SEQ;

    for (int l0 = 0; l0 < L_SEQ; l0 += 16) {
#pragma unroll
        for (int j = 0; j < 16; j++) {
            int l = l0 + j;
            float v = xp[(size_t)l * C_TAB];
            if (v > cmax) { cmax = v; carg = l; }   // first-occurrence ties
            csum += v;
            bool pad = (l < L_SEQ - 1);
            float pm = pad ? fmaxf(cmax, 0.0f) : cmax;
            int   ti = (pad && (cmax <= 0.0f)) ? (l - (L_SEQ - 1)) : carg;
            pm_p[(size_t)l * C_TAB] = pm;
            pa_p[(size_t)l * C_TAB] = csum * (1.0f / (float)L_SEQ);
            ps_p[(size_t)l * C_TAB] = csum * rsqrtf((float)(l + 1));
            s_act[c][j] = pm;
            s_idx[c][j] = ti;
        }
        __syncthreads();
        int jj = c & 15;
        int r0 = c >> 4;
#pragma unroll
        for (int i = 0; i < 16; i++) {
            int c2 = r0 * 16 + i;
            size_t off = obase + (size_t)c2 * L_SEQ + l0 + jj;
            act_out[off]  = s_act[c2][jj];
            tind_out[off] = (float)s_idx[c2][jj];
        }
        __syncthreads();
    }
}

// ============================================================
// Kernel 4: LayerNorm over channels + assemble output rows.
// One block per (n,l) row; fused 6-way reduction.
// ============================================================
__global__ __launch_bounds__(256) void k_ln(float* __restrict__ out) {
    const int m = blockIdx.x;       // 0..65535
    const int c = threadIdx.x;
    const size_t base = (size_t)m * C_TAB + c;
    float vm = g_pmax[base];
    float va = g_pavg[base];
    float vs = g_psum[base];

    float s[6] = { vm, vm * vm, va, va * va, vs, vs * vs };
#pragma unroll
    for (int o = 16; o > 0; o >>= 1)
#pragma unroll
        for (int q = 0; q < 6; q++)
            s[q] += __shfl_xor_sync(0xffffffffu, s[q], o);

    __shared__ float red[8][6];
    int warp = c >> 5, lane = c & 31;
    if (lane == 0) {
#pragma unroll
        for (int q = 0; q < 6; q++) red[warp][q] = s[q];
    }
    __syncthreads();
    float t[6];
#pragma unroll
    for (int q = 0; q < 6; q++) {
        float a = 0.0f;
#pragma unroll
        for (int w = 0; w < 8; w++) a += red[w][q];
        t[q] = a;
    }
    const float inv = 1.0f / (float)C_TAB;
    float mu_m = t[0] * inv, var_m = t[1] * inv - mu_m * mu_m;
    float mu_a = t[2] * inv, var_a = t[3] * inv - mu_a * mu_a;
    float mu_s = t[4] * inv, var_s = t[5] * inv - mu_s * mu_s;
    float rs_m = rsqrtf(var_m + 1e-5f);
    float rs_a = rsqrtf(var_a + 1e-5f);
    float rs_s = rsqrtf(var_s + 1e-5f);

    const size_t ob = (size_t)m * OUT_C;
    out[ob + c]       = (vm - mu_m) * rs_m;
    out[ob + 256 + c] = (va - mu_a) * rs_a;
    out[ob + 512 + c] = (vs - mu_s) * rs_s;
    if (c < DEM_OUT)
        out[ob + 768 + c] = g_d[(m >> 11) * DEM_OUT + c];
}

// ============================================================
extern "C" void kernel_launch(void* const* d_in, const int* in_sizes, int n_in,
                              void* d_out, int out_size) {
    (void)in_sizes; (void)n_in; (void)out_size;
    const float* dem = (const float*)d_in[0];
    const float* t0  = (const float*)d_in[1];
    const float* t1  = (const float*)d_in[2];
    const float* t2  = (const float*)d_in[3];
    const float* t3  = (const float*)d_in[4];
    const float* W1  = (const float*)d_in[5];
    const float* b1  = (const float*)d_in[6];
    const float* W2  = (const float*)d_in[7];
    const float* b2  = (const float*)d_in[8];
    const float* Wl  = (const float*)d_in[9];
    const float* bl  = (const float*)d_in[10];

    float* out  = (float*)d_out;                                   // [32,2048,788]
    float* tind = out  + (size_t)N_PAT * L_SEQ * OUT_C;            // [32,256,2048]
    float* act  = tind + (size_t)N_PAT * C_TAB * L_SEQ;            // [32,256,2048]

    k_dem<<<1, 256>>>(dem, W1, b1, W2, b2, Wl, bl);
    k_gemm<<<dim3(2, 512), 256>>>(t0, t1, t2, t3, Wl);
    k_scan<<<N_PAT, 256>>>(tind, act);
    k_ln<<<M_TOT, 256>>>(out);
}